// round 16
// baseline (speedup 1.0000x reference)
#include <cuda_runtime.h>
#include <cuda_fp16.h>
#include <math.h>
#include <stdint.h>

// Problem constants
#define BATCH 2
#define CC    128
#define HH    48
#define WF    160
#define ND_   161
#define NW_   161
#define DD    160
#define WW    160
#define KDIM  512
#define CH    512
#define MROWS (BATCH*DD*WW)     // 51200
#define NCELL (BATCH*4*DD*WW)   // 204800
#define PLANE (WW*DD)           // 25600

// Static device scratch
__device__ float  g_integral[(size_t)BATCH*HH*WF*CC];  // NHWC
__device__ __half g_vox[(size_t)MROWS*KDIM];           // [M][K] fp16
__device__ __half g_wlT[(size_t)CH*KDIM];              // [N][K] permuted fp16
__device__ float2 g_tap[(size_t)16*NCELL];             // SoA: [tap][cell] {w, idx}
__device__ int    g_tcnt[NCELL];                       // padded tap count

// ---------------------------------------------------------------------------
// bbox helper: projection + merged separable taps
// ---------------------------------------------------------------------------
__device__ __forceinline__ void project_pt(const float* __restrict__ cal,
                                           float X, float Y, float Z,
                                           float& nx, float& ny) {
    float h0 = cal[0]*X + cal[1]*Y + cal[2]*Z  + cal[3];
    float h1 = cal[4]*X + cal[5]*Y + cal[6]*Z  + cal[7];
    float h2 = cal[8]*X + cal[9]*Y + cal[10]*Z + cal[11];
    float ix = h0 / h2;
    float iy = h1 / h2;
    nx = fminf(fmaxf(2.0f*ix/(float)WF - 1.0f, -1.f), 1.f);
    ny = fminf(fmaxf(2.0f*iy/(float)HH - 1.0f, -1.f), 1.f);
}

__device__ __forceinline__ void bbox_cell(int cell,
                                          const float* __restrict__ calib,
                                          const float* __restrict__ corners) {
    int w = cell % WW;
    int d = (cell / WW) % DD;
    int y = (cell / (WW*DD)) & 3;
    int b = cell / (WW*DD*4);
    const float* cal = calib + b*12;

    float ax, ay, bx, by, cx2, cy2, dx2, dy2;
    { const float* p = corners + (((size_t)y*ND_ + d)*NW_ + w)*3;
      project_pt(cal, p[0], p[1], p[2], ax, ay); }
    { const float* p = corners + (((size_t)y*ND_ + (d+1))*NW_ + w)*3;
      project_pt(cal, p[0], p[1], p[2], bx, by); }
    { const float* p = corners + (((size_t)(y+1)*ND_ + (d+1))*NW_ + (w+1))*3;
      project_pt(cal, p[0], p[1], p[2], cx2, cy2); }
    { const float* p = corners + (((size_t)(y+1)*ND_ + d)*NW_ + (w+1))*3;
      project_pt(cal, p[0], p[1], p[2], dx2, dy2); }

    float x0 = fminf(ax, bx),   y0v = fminf(ay, by);
    float x1 = fmaxf(cx2, dx2), y1v = fmaxf(cy2, dy2);

    float area = (x1 - x0) * (y1v - y0v) * ((float)HH * (float)WF * 0.25f) + 1e-6f;
    float inv  = (area > 1e-6f) ? (1.f / area) : 0.f;

    float gx0 = (x0 + 1.f)*((float)WF*0.5f) - 0.5f;
    float gx1 = (x1 + 1.f)*((float)WF*0.5f) - 0.5f;
    float fx0f = floorf(gx0), fx1f = floorf(gx1);
    float fx0 = gx0 - fx0f, fx1 = gx1 - fx1f;
    int ix0 = (int)fx0f, ix1 = (int)fx1f;
    int   cxi[4] = {ix0, ix0 + 1, ix1, ix1 + 1};
    float u[4]   = {-(1.f - fx0), -fx0, (1.f - fx1), fx1};
    float gy0 = (y0v + 1.f)*((float)HH*0.5f) - 0.5f;
    float gy1 = (y1v + 1.f)*((float)HH*0.5f) - 0.5f;
    float fy0f = floorf(gy0), fy1f = floorf(gy1);
    float fy0 = gy0 - fy0f, fy1 = gy1 - fy1f;
    int iy0 = (int)fy0f, iy1 = (int)fy1f;
    int   ryi[4] = {iy0, iy0 + 1, iy1, iy1 + 1};
    float v[4]   = {-(1.f - fy0), -fy0, (1.f - fy1), fy1};

    #pragma unroll
    for (int i = 1; i < 4; i++)
        #pragma unroll
        for (int j = 0; j < i; j++)
            if (cxi[i] == cxi[j]) { u[j] += u[i]; u[i] = 0.f; cxi[i] = -1000000; }
    #pragma unroll
    for (int i = 1; i < 4; i++)
        #pragma unroll
        for (int j = 0; j < i; j++)
            if (ryi[i] == ryi[j]) { v[j] += v[i]; v[i] = 0.f; ryi[i] = -1000000; }

    int   colo[4]; float colw[4]; int nC = 0;
    #pragma unroll
    for (int i = 0; i < 4; i++)
        if (u[i] != 0.f && cxi[i] >= 0 && cxi[i] < WF) {
            colo[nC] = cxi[i]; colw[nC] = u[i]; nC++;
        }
    int   rowo[4]; float roww[4]; int nR = 0;
    #pragma unroll
    for (int i = 0; i < 4; i++)
        if (v[i] != 0.f && ryi[i] >= 0 && ryi[i] < HH) {
            rowo[nR] = (b*HH + ryi[i])*WF; roww[nR] = v[i]; nR++;
        }

    int nt = (inv != 0.f) ? nR*nC : 0;
    int t = 0;
    for (int r = 0; r < nR && t < nt; r++)
        for (int c = 0; c < nC && t < nt; c++, t++) {
            float2 tp;
            tp.x = roww[r]*colw[c]*inv;
            tp.y = __int_as_float((rowo[r] + colo[c])*CC);
            g_tap[(size_t)t*NCELL + cell] = tp;
        }
    int ntp = (nt + 3) & ~3;              // pad to multiple of 4
    for (; t < ntp; t++) {
        float2 tp; tp.x = 0.f; tp.y = __int_as_float(0);
        g_tap[(size_t)t*NCELL + cell] = tp;
    }
    g_tcnt[cell] = ntp;
}

// ---------------------------------------------------------------------------
// k_prep: [0,192) cumsum-W + transpose; [192,1216) wperm; [1216,2016) bbox.
// ---------------------------------------------------------------------------
#define NPREP_CW (BATCH*HH*2)              // 192
#define NPREP_WP ((KDIM*CH)/256)           // 1024
#define NPREP_BB (NCELL/256)               // 800
#define NPREP_TOTAL (NPREP_CW + NPREP_WP + NPREP_BB)

__global__ __launch_bounds__(256) void k_prep(const float* __restrict__ feat,
                                              const float* __restrict__ Wl,
                                              const float* __restrict__ calib,
                                              const float* __restrict__ corners) {
    __shared__ float S[64][WF + 1];
    int tid = threadIdx.x;
    if (blockIdx.x < NPREP_CW) {
        int blk = blockIdx.x;
        int b    = blk / (HH*2);
        int rem  = blk % (HH*2);
        int h    = rem >> 1;
        int c0   = (rem & 1) * 64;

        #pragma unroll
        for (int i = 0; i < 40; i++) {
            int idx = i*256 + tid;
            int c = idx / WF;
            int w = idx - c*WF;
            S[c][w] = feat[((size_t)(b*CC + c0 + c)*HH + h)*WF + w];
        }
        __syncthreads();
        if (tid < 64) {
            float acc = 0.f;
            #pragma unroll 8
            for (int w = 0; w < WF; w++) { acc += S[tid][w]; S[tid][w] = acc; }
        }
        __syncthreads();
        #pragma unroll
        for (int i = 0; i < 40; i++) {
            int idx = i*256 + tid;
            int w = idx >> 6;
            int c = idx & 63;
            g_integral[((size_t)(b*HH + h)*WF + w)*CC + c0 + c] = S[c][w];
        }
    } else if (blockIdx.x < NPREP_CW + NPREP_WP) {
        int i = (blockIdx.x - NPREP_CW)*256 + tid;   // 0..262143
        int n  = i >> 9;
        int kk = i & 511;
        int wrow = ((kk & 127) << 2) + (kk >> 7);
        g_wlT[i] = __float2half(Wl[(size_t)wrow*CH + n]);
    } else {
        int cell = (blockIdx.x - NPREP_CW - NPREP_WP)*256 + tid;
        if (cell < NCELL) bbox_cell(cell, calib, corners);
    }
}

// cumsum along H in place (coalesced along c in NHWC)
__global__ void k_cumsum_h() {
    int bw = blockIdx.x;
    int b = bw / WF, w = bw % WF;
    int c = threadIdx.x;
    float* p = g_integral + (((size_t)b*HH)*WF + w)*CC + c;
    const size_t stride = (size_t)WF*CC;
    float acc = 0.f;
    #pragma unroll 6
    for (int h = 0; h < HH; h++) {
        acc += p[h*stride];
        p[h*stride] = acc;
    }
}

// ---------------------------------------------------------------------------
// Sampler: 32 threads/cell, float4/thread. ALL 16 tap loads hoisted;
// gathers predicated per batch of 4 on the warp-uniform count.
// ---------------------------------------------------------------------------
__global__ __launch_bounds__(256) void k_sample() {
    int cell = blockIdx.x*8 + (threadIdx.x >> 5);
    int c4 = (threadIdx.x & 31) * 4;

    const int nt = __ldg(&g_tcnt[cell]);   // warp-uniform, multiple of 4
    float4 a0 = make_float4(0.f, 0.f, 0.f, 0.f);
    float4 a1 = make_float4(0.f, 0.f, 0.f, 0.f);

    if (nt != 0) {
        float2 t[16];
        #pragma unroll
        for (int i = 0; i < 16; i++)
            t[i] = __ldg(&g_tap[(size_t)i*NCELL + cell]);

        #pragma unroll
        for (int bb = 0; bb < 4; bb++) {
            if (bb == 0 || nt > bb*4) {
                const float2 t0 = t[bb*4+0], t1 = t[bb*4+1];
                const float2 t2 = t[bb*4+2], t3 = t[bb*4+3];
                const float4 v0 = *(const float4*)&g_integral[__float_as_int(t0.y) + c4];
                const float4 v1 = *(const float4*)&g_integral[__float_as_int(t1.y) + c4];
                const float4 v2 = *(const float4*)&g_integral[__float_as_int(t2.y) + c4];
                const float4 v3 = *(const float4*)&g_integral[__float_as_int(t3.y) + c4];
                a0.x += t0.x*v0.x; a0.y += t0.x*v0.y; a0.z += t0.x*v0.z; a0.w += t0.x*v0.w;
                a1.x += t1.x*v1.x; a1.y += t1.x*v1.y; a1.z += t1.x*v1.z; a1.w += t1.x*v1.w;
                a0.x += t2.x*v2.x; a0.y += t2.x*v2.y; a0.z += t2.x*v2.z; a0.w += t2.x*v2.w;
                a1.x += t3.x*v3.x; a1.y += t3.x*v3.y; a1.z += t3.x*v3.z; a1.w += t3.x*v3.w;
            }
        }
    }
    float4 acc;
    acc.x = a0.x + a1.x; acc.y = a0.y + a1.y;
    acc.z = a0.z + a1.z; acc.w = a0.w + a1.w;

    int w = cell % WW;
    int d = (cell / WW) % DD;
    int y = (cell / (WW*DD)) & 3;
    int b = cell / (WW*DD*4);
    int row = (b*WW + w)*DD + d;
    __half2 lo = __floats2half2_rn(acc.x, acc.y);
    __half2 hi = __floats2half2_rn(acc.z, acc.w);
    uint2 pk;
    pk.x = *(uint32_t*)&lo;
    pk.y = *(uint32_t*)&hi;
    *(uint2*)&g_vox[(size_t)row*KDIM + y*CC + c4] = pk;
}

// ---------------------------------------------------------------------------
// fp16 tensor-core GEMM: CTA tile 128x256, 8 warps (2m x 4n), warp tile
// 64x64 (CUTLASS sm80 shape). BK=32, 4-stage cp.async (wait_group 2, one
// commit per iter). -33% smem read traffic vs 64x32 warp tiles.
// out = relu(vox@W + bias), fused transpose. 1 CTA/SM.
// ---------------------------------------------------------------------------
#define BM 128
#define BN 256
#define BK 32
#define KSTRIDE 40                       // halves; 80B rows, conflict-free
#define ABUF_BYTES (BM*KSTRIDE*2)        // 10240
#define BBUF_BYTES (BN*KSTRIDE*2)        // 20480
#define STAGE_BYTES (ABUF_BYTES+BBUF_BYTES) // 30720
#define NSTAGE 4
#define GEMM_SMEM (NSTAGE*STAGE_BYTES)   // 122880

__device__ __forceinline__ void cp16(uint32_t smem, const void* gmem) {
    asm volatile("cp.async.ca.shared.global [%0], [%1], 16;\n" :: "r"(smem), "l"(gmem));
}
__device__ __forceinline__ void cp_commit() {
    asm volatile("cp.async.commit_group;\n" ::: "memory");
}
template<int N> __device__ __forceinline__ void cp_wait() {
    asm volatile("cp.async.wait_group %0;\n" :: "n"(N) : "memory");
}
__device__ __forceinline__ void ldsm_x4(uint32_t& r0, uint32_t& r1,
                                        uint32_t& r2, uint32_t& r3, uint32_t addr) {
    asm volatile("ldmatrix.sync.aligned.m8n8.x4.shared.b16 {%0,%1,%2,%3}, [%4];"
                 : "=r"(r0), "=r"(r1), "=r"(r2), "=r"(r3) : "r"(addr));
}
__device__ __forceinline__ void mma_f16(float* c, const uint32_t* a, const uint32_t* b) {
    asm volatile(
        "mma.sync.aligned.m16n8k16.row.col.f32.f16.f16.f32 "
        "{%0,%1,%2,%3}, {%4,%5,%6,%7}, {%8,%9}, {%0,%1,%2,%3};\n"
        : "+f"(c[0]), "+f"(c[1]), "+f"(c[2]), "+f"(c[3])
        : "r"(a[0]), "r"(a[1]), "r"(a[2]), "r"(a[3]), "r"(b[0]), "r"(b[1]));
}

__global__ __launch_bounds__(256, 1) void k_gemm(const float* __restrict__ bias,
                                                 float* __restrict__ out) {
    extern __shared__ __align__(16) __half smem[];

    const int n0 = blockIdx.x * BN;   // 2 blocks
    const int m0 = blockIdx.y * BM;   // 400 blocks
    const int tid = threadIdx.x;
    const int wid = tid >> 5;
    const int lane = tid & 31;
    const int g  = lane >> 2;
    const int tg = lane & 3;
    const int mbase = (wid >> 2) * 64;   // 2 warp rows
    const int nbase = (wid & 3) * 64;    // 4 warp cols

    const uint32_t smem_base = (uint32_t)__cvta_generic_to_shared(smem);

    // cp.async addressing: A 2x16B/thread (rows 0..127), B 4x16B/thread (rows 0..255)
    const int ld_row0 = tid >> 2;             // 0..63
    const int ld_seg  = (tid & 3) * 8;        // half col 0,8,16,24
    const uint32_t stA0 = smem_base + (uint32_t)(ld_row0*KSTRIDE + ld_seg)*2;
    const uint32_t stA1 = smem_base + (uint32_t)((ld_row0+64)*KSTRIDE + ld_seg)*2;
    uint32_t stB[4];
    #pragma unroll
    for (int i = 0; i < 4; i++)
        stB[i] = smem_base + ABUF_BYTES +
                 (uint32_t)((ld_row0 + i*64)*KSTRIDE + ld_seg)*2;

    // ldmatrix bases (stage 0)
    uint32_t lmA[4];
    #pragma unroll
    for (int mi = 0; mi < 4; mi++)
        lmA[mi] = smem_base +
            (uint32_t)((mbase + mi*16 + (lane & 15))*KSTRIDE + ((lane >> 4) << 3))*2;
    uint32_t lmB[4];
    #pragma unroll
    for (int p = 0; p < 4; p++)
        lmB[p] = smem_base + ABUF_BYTES +
            (uint32_t)((nbase + p*16 + (((lane >> 4) & 1) << 3) + (lane & 7))*KSTRIDE
                       + (((lane >> 3) & 1) << 3))*2;

    float acc[4][8][4];
    #pragma unroll
    for (int mi = 0; mi < 4; mi++)
        #pragma unroll
        for (int ni = 0; ni < 8; ni++)
            #pragma unroll
            for (int r = 0; r < 4; r++) acc[mi][ni][r] = 0.f;

    const int NCHUNK = KDIM / BK;     // 16
    auto load_chunk = [&](int c) {
        if (c < NCHUNK) {
            uint32_t so = (uint32_t)(c % NSTAGE) * STAGE_BYTES;
            int kb = c * BK;
            cp16(stA0 + so, g_vox + (size_t)(m0 + ld_row0)*KDIM + kb + ld_seg);
            cp16(stA1 + so, g_vox + (size_t)(m0 + ld_row0 + 64)*KDIM + kb + ld_seg);
            #pragma unroll
            for (int i = 0; i < 4; i++)
                cp16(stB[i] + so,
                     g_wlT + (size_t)(n0 + ld_row0 + i*64)*KDIM + kb + ld_seg);
        }
        cp_commit();
    };

    load_chunk(0);
    load_chunk(1);
    load_chunk(2);

    for (int c = 0; c < NCHUNK; c++) {
        cp_wait<2>();                 // chunk c resident
        __syncthreads();              // WAR guard on stage (c+3)%4

        load_chunk(c + 3);

        const uint32_t so = (uint32_t)(c % NSTAGE) * STAGE_BYTES;
        #pragma unroll
        for (int kc = 0; kc < BK; kc += 16) {
            uint32_t a[4][4], b[8][2];
            #pragma unroll
            for (int mi = 0; mi < 4; mi++)
                ldsm_x4(a[mi][0], a[mi][1], a[mi][2], a[mi][3],
                        lmA[mi] + so + kc*2);
            #pragma unroll
            for (int p = 0; p < 4; p++)
                ldsm_x4(b[2*p][0], b[2*p][1], b[2*p+1][0], b[2*p+1][1],
                        lmB[p] + so + kc*2);
            #pragma unroll
            for (int mi = 0; mi < 4; mi++)
                #pragma unroll
                for (int ni = 0; ni < 8; ni++)
                    mma_f16(acc[mi][ni], a[mi], b[ni]);
        }
    }

    // Epilogue: bias + relu + transposed store (coalesced along M)
    const int bidx  = m0 / PLANE;
    const int mrel0 = m0 - bidx*PLANE + mbase;
    #pragma unroll
    for (int ni = 0; ni < 8; ni++) {
        int n_e = n0 + nbase + ni*8 + 2*tg;
        float be = bias[n_e];
        float bo = bias[n_e + 1];
        float* ope = out + ((size_t)(bidx*CH + n_e))*PLANE;
        float* opo = ope + PLANE;
        #pragma unroll
        for (int mi = 0; mi < 4; mi++) {
            int moff = mrel0 + mi*16 + g;
            ope[moff    ] = fmaxf(acc[mi][ni][0] + be, 0.f);
            opo[moff    ] = fmaxf(acc[mi][ni][1] + bo, 0.f);
            ope[moff + 8] = fmaxf(acc[mi][ni][2] + be, 0.f);
            opo[moff + 8] = fmaxf(acc[mi][ni][3] + bo, 0.f);
        }
    }
}

// ---------------------------------------------------------------------------
extern "C" void kernel_launch(void* const* d_in, const int* in_sizes, int n_in,
                              void* d_out, int out_size) {
    const float* features = (const float*)d_in[0];   // [2,128,48,160]
    const float* calib    = (const float*)d_in[1];   // [2,3,4]
    const float* corners  = (const float*)d_in[2];   // [1,5,161,161,3]
    const float* W_lin    = (const float*)d_in[3];   // [512,512]
    const float* b_lin    = (const float*)d_in[4];   // [512]
    float* out = (float*)d_out;                      // [2,512,160,160]

    cudaFuncSetAttribute(k_gemm, cudaFuncAttributeMaxDynamicSharedMemorySize,
                         GEMM_SMEM);

    // 4 launches; k_gemm is the 4th (ncu capture window).
    k_prep<<<NPREP_TOTAL, 256>>>(features, W_lin, calib, corners);
    k_cumsum_h<<<BATCH*WF, CC>>>();
    k_sample<<<NCELL/8, 256>>>();
    k_gemm<<<dim3(CH/BN, MROWS/BM), 256, GEMM_SMEM>>>(b_lin, out);
}

// round 17
// speedup vs baseline: 1.0396x; 1.0396x over previous
#include <cuda_runtime.h>
#include <cuda_fp16.h>
#include <math.h>
#include <stdint.h>

// Problem constants
#define BATCH 2
#define CC    128
#define HH    48
#define WF    160
#define ND_   161
#define NW_   161
#define DD    160
#define WW    160
#define KDIM  512
#define CH    512
#define MROWS (BATCH*DD*WW)     // 51200
#define NCELL (BATCH*4*DD*WW)   // 204800
#define PLANE (WW*DD)           // 25600

// Static device scratch
__device__ float  g_integral[(size_t)BATCH*HH*WF*CC];  // NHWC
__device__ __half g_vox[(size_t)MROWS*KDIM];           // [M][K] fp16
__device__ __half g_wlT[(size_t)CH*KDIM];              // [N][K] permuted fp16
__device__ float2 g_tap[(size_t)16*NCELL];             // SoA: [tap][cell] {w, idx}
__device__ int    g_tcnt[NCELL];                       // padded tap count

// ---------------------------------------------------------------------------
// bbox helper: projection + merged separable taps
// ---------------------------------------------------------------------------
__device__ __forceinline__ void project_pt(const float* __restrict__ cal,
                                           float X, float Y, float Z,
                                           float& nx, float& ny) {
    float h0 = cal[0]*X + cal[1]*Y + cal[2]*Z  + cal[3];
    float h1 = cal[4]*X + cal[5]*Y + cal[6]*Z  + cal[7];
    float h2 = cal[8]*X + cal[9]*Y + cal[10]*Z + cal[11];
    float ix = h0 / h2;
    float iy = h1 / h2;
    nx = fminf(fmaxf(2.0f*ix/(float)WF - 1.0f, -1.f), 1.f);
    ny = fminf(fmaxf(2.0f*iy/(float)HH - 1.0f, -1.f), 1.f);
}

__device__ __forceinline__ void bbox_cell(int cell,
                                          const float* __restrict__ calib,
                                          const float* __restrict__ corners) {
    int w = cell % WW;
    int d = (cell / WW) % DD;
    int y = (cell / (WW*DD)) & 3;
    int b = cell / (WW*DD*4);
    const float* cal = calib + b*12;

    float ax, ay, bx, by, cx2, cy2, dx2, dy2;
    { const float* p = corners + (((size_t)y*ND_ + d)*NW_ + w)*3;
      project_pt(cal, p[0], p[1], p[2], ax, ay); }
    { const float* p = corners + (((size_t)y*ND_ + (d+1))*NW_ + w)*3;
      project_pt(cal, p[0], p[1], p[2], bx, by); }
    { const float* p = corners + (((size_t)(y+1)*ND_ + (d+1))*NW_ + (w+1))*3;
      project_pt(cal, p[0], p[1], p[2], cx2, cy2); }
    { const float* p = corners + (((size_t)(y+1)*ND_ + d)*NW_ + (w+1))*3;
      project_pt(cal, p[0], p[1], p[2], dx2, dy2); }

    float x0 = fminf(ax, bx),   y0v = fminf(ay, by);
    float x1 = fmaxf(cx2, dx2), y1v = fmaxf(cy2, dy2);

    float area = (x1 - x0) * (y1v - y0v) * ((float)HH * (float)WF * 0.25f) + 1e-6f;
    float inv  = (area > 1e-6f) ? (1.f / area) : 0.f;

    float gx0 = (x0 + 1.f)*((float)WF*0.5f) - 0.5f;
    float gx1 = (x1 + 1.f)*((float)WF*0.5f) - 0.5f;
    float fx0f = floorf(gx0), fx1f = floorf(gx1);
    float fx0 = gx0 - fx0f, fx1 = gx1 - fx1f;
    int ix0 = (int)fx0f, ix1 = (int)fx1f;
    int   cxi[4] = {ix0, ix0 + 1, ix1, ix1 + 1};
    float u[4]   = {-(1.f - fx0), -fx0, (1.f - fx1), fx1};
    float gy0 = (y0v + 1.f)*((float)HH*0.5f) - 0.5f;
    float gy1 = (y1v + 1.f)*((float)HH*0.5f) - 0.5f;
    float fy0f = floorf(gy0), fy1f = floorf(gy1);
    float fy0 = gy0 - fy0f, fy1 = gy1 - fy1f;
    int iy0 = (int)fy0f, iy1 = (int)fy1f;
    int   ryi[4] = {iy0, iy0 + 1, iy1, iy1 + 1};
    float v[4]   = {-(1.f - fy0), -fy0, (1.f - fy1), fy1};

    #pragma unroll
    for (int i = 1; i < 4; i++)
        #pragma unroll
        for (int j = 0; j < i; j++)
            if (cxi[i] == cxi[j]) { u[j] += u[i]; u[i] = 0.f; cxi[i] = -1000000; }
    #pragma unroll
    for (int i = 1; i < 4; i++)
        #pragma unroll
        for (int j = 0; j < i; j++)
            if (ryi[i] == ryi[j]) { v[j] += v[i]; v[i] = 0.f; ryi[i] = -1000000; }

    int   colo[4]; float colw[4]; int nC = 0;
    #pragma unroll
    for (int i = 0; i < 4; i++)
        if (u[i] != 0.f && cxi[i] >= 0 && cxi[i] < WF) {
            colo[nC] = cxi[i]; colw[nC] = u[i]; nC++;
        }
    int   rowo[4]; float roww[4]; int nR = 0;
    #pragma unroll
    for (int i = 0; i < 4; i++)
        if (v[i] != 0.f && ryi[i] >= 0 && ryi[i] < HH) {
            rowo[nR] = (b*HH + ryi[i])*WF; roww[nR] = v[i]; nR++;
        }

    int nt = (inv != 0.f) ? nR*nC : 0;
    int t = 0;
    for (int r = 0; r < nR && t < nt; r++)
        for (int c = 0; c < nC && t < nt; c++, t++) {
            float2 tp;
            tp.x = roww[r]*colw[c]*inv;
            tp.y = __int_as_float((rowo[r] + colo[c])*CC);
            g_tap[(size_t)t*NCELL + cell] = tp;
        }
    int ntp = (nt + 3) & ~3;              // pad to multiple of 4
    for (; t < ntp; t++) {
        float2 tp; tp.x = 0.f; tp.y = __int_as_float(0);
        g_tap[(size_t)t*NCELL + cell] = tp;
    }
    g_tcnt[cell] = ntp;
}

// ---------------------------------------------------------------------------
// k_prep: [0,192) cumsum-W + transpose; [192,1216) wperm; [1216,2016) bbox.
// ---------------------------------------------------------------------------
#define NPREP_CW (BATCH*HH*2)              // 192
#define NPREP_WP ((KDIM*CH)/256)           // 1024
#define NPREP_BB (NCELL/256)               // 800
#define NPREP_TOTAL (NPREP_CW + NPREP_WP + NPREP_BB)

__global__ __launch_bounds__(256) void k_prep(const float* __restrict__ feat,
                                              const float* __restrict__ Wl,
                                              const float* __restrict__ calib,
                                              const float* __restrict__ corners) {
    __shared__ float S[64][WF + 1];
    int tid = threadIdx.x;
    if (blockIdx.x < NPREP_CW) {
        int blk = blockIdx.x;
        int b    = blk / (HH*2);
        int rem  = blk % (HH*2);
        int h    = rem >> 1;
        int c0   = (rem & 1) * 64;

        #pragma unroll
        for (int i = 0; i < 40; i++) {
            int idx = i*256 + tid;
            int c = idx / WF;
            int w = idx - c*WF;
            S[c][w] = feat[((size_t)(b*CC + c0 + c)*HH + h)*WF + w];
        }
        __syncthreads();
        if (tid < 64) {
            float acc = 0.f;
            #pragma unroll 8
            for (int w = 0; w < WF; w++) { acc += S[tid][w]; S[tid][w] = acc; }
        }
        __syncthreads();
        #pragma unroll
        for (int i = 0; i < 40; i++) {
            int idx = i*256 + tid;
            int w = idx >> 6;
            int c = idx & 63;
            g_integral[((size_t)(b*HH + h)*WF + w)*CC + c0 + c] = S[c][w];
        }
    } else if (blockIdx.x < NPREP_CW + NPREP_WP) {
        int i = (blockIdx.x - NPREP_CW)*256 + tid;   // 0..262143
        int n  = i >> 9;
        int kk = i & 511;
        int wrow = ((kk & 127) << 2) + (kk >> 7);
        g_wlT[i] = __float2half(Wl[(size_t)wrow*CH + n]);
    } else {
        int cell = (blockIdx.x - NPREP_CW - NPREP_WP)*256 + tid;
        if (cell < NCELL) bbox_cell(cell, calib, corners);
    }
}

// cumsum along H in place (coalesced along c in NHWC)
__global__ void k_cumsum_h() {
    int bw = blockIdx.x;
    int b = bw / WF, w = bw % WF;
    int c = threadIdx.x;
    float* p = g_integral + (((size_t)b*HH)*WF + w)*CC + c;
    const size_t stride = (size_t)WF*CC;
    float acc = 0.f;
    #pragma unroll 6
    for (int h = 0; h < HH; h++) {
        acc += p[h*stride];
        p[h*stride] = acc;
    }
}

// ---------------------------------------------------------------------------
// Sampler: 32 threads/cell, float4/thread. ALL 16 tap loads hoisted;
// gathers predicated per batch of 4 on the warp-uniform count.
// ---------------------------------------------------------------------------
__global__ __launch_bounds__(256) void k_sample() {
    int cell = blockIdx.x*8 + (threadIdx.x >> 5);
    int c4 = (threadIdx.x & 31) * 4;

    const int nt = __ldg(&g_tcnt[cell]);   // warp-uniform, multiple of 4
    float4 a0 = make_float4(0.f, 0.f, 0.f, 0.f);
    float4 a1 = make_float4(0.f, 0.f, 0.f, 0.f);

    if (nt != 0) {
        float2 t[16];
        #pragma unroll
        for (int i = 0; i < 16; i++)
            t[i] = __ldg(&g_tap[(size_t)i*NCELL + cell]);

        #pragma unroll
        for (int bb = 0; bb < 4; bb++) {
            if (bb == 0 || nt > bb*4) {
                const float2 t0 = t[bb*4+0], t1 = t[bb*4+1];
                const float2 t2 = t[bb*4+2], t3 = t[bb*4+3];
                const float4 v0 = *(const float4*)&g_integral[__float_as_int(t0.y) + c4];
                const float4 v1 = *(const float4*)&g_integral[__float_as_int(t1.y) + c4];
                const float4 v2 = *(const float4*)&g_integral[__float_as_int(t2.y) + c4];
                const float4 v3 = *(const float4*)&g_integral[__float_as_int(t3.y) + c4];
                a0.x += t0.x*v0.x; a0.y += t0.x*v0.y; a0.z += t0.x*v0.z; a0.w += t0.x*v0.w;
                a1.x += t1.x*v1.x; a1.y += t1.x*v1.y; a1.z += t1.x*v1.z; a1.w += t1.x*v1.w;
                a0.x += t2.x*v2.x; a0.y += t2.x*v2.y; a0.z += t2.x*v2.z; a0.w += t2.x*v2.w;
                a1.x += t3.x*v3.x; a1.y += t3.x*v3.y; a1.z += t3.x*v3.z; a1.w += t3.x*v3.w;
            }
        }
    }
    float4 acc;
    acc.x = a0.x + a1.x; acc.y = a0.y + a1.y;
    acc.z = a0.z + a1.z; acc.w = a0.w + a1.w;

    int w = cell % WW;
    int d = (cell / WW) % DD;
    int y = (cell / (WW*DD)) & 3;
    int b = cell / (WW*DD*4);
    int row = (b*WW + w)*DD + d;
    __half2 lo = __floats2half2_rn(acc.x, acc.y);
    __half2 hi = __floats2half2_rn(acc.z, acc.w);
    uint2 pk;
    pk.x = *(uint32_t*)&lo;
    pk.y = *(uint32_t*)&hi;
    *(uint2*)&g_vox[(size_t)row*KDIM + y*CC + c4] = pk;
}

// ---------------------------------------------------------------------------
// fp16 tensor-core GEMM: CTA 128x128, 4 warps (2m x 2n), warp tile 64x64.
// Same smem-traffic ratio as a 128x256 tile (-33% vs 64x32 warps) but with
// 2 CTAs/SM (8 warps/SM) for latency hiding. BK=32, 4-stage cp.async
// (wait_group 2, one commit per iter). out = relu(vox@W+bias), fused
// transpose.
// ---------------------------------------------------------------------------
#define BM 128
#define BN 128
#define BK 32
#define KSTRIDE 40                       // halves; 80B rows, conflict-free
#define ABUF_BYTES (BM*KSTRIDE*2)        // 10240
#define STAGE_BYTES (2*ABUF_BYTES)       // 20480 (A+B)
#define NSTAGE 4
#define GEMM_SMEM (NSTAGE*STAGE_BYTES)   // 81920

__device__ __forceinline__ void cp16(uint32_t smem, const void* gmem) {
    asm volatile("cp.async.ca.shared.global [%0], [%1], 16;\n" :: "r"(smem), "l"(gmem));
}
__device__ __forceinline__ void cp_commit() {
    asm volatile("cp.async.commit_group;\n" ::: "memory");
}
template<int N> __device__ __forceinline__ void cp_wait() {
    asm volatile("cp.async.wait_group %0;\n" :: "n"(N) : "memory");
}
__device__ __forceinline__ void ldsm_x4(uint32_t& r0, uint32_t& r1,
                                        uint32_t& r2, uint32_t& r3, uint32_t addr) {
    asm volatile("ldmatrix.sync.aligned.m8n8.x4.shared.b16 {%0,%1,%2,%3}, [%4];"
                 : "=r"(r0), "=r"(r1), "=r"(r2), "=r"(r3) : "r"(addr));
}
__device__ __forceinline__ void mma_f16(float* c, const uint32_t* a, const uint32_t* b) {
    asm volatile(
        "mma.sync.aligned.m16n8k16.row.col.f32.f16.f16.f32 "
        "{%0,%1,%2,%3}, {%4,%5,%6,%7}, {%8,%9}, {%0,%1,%2,%3};\n"
        : "+f"(c[0]), "+f"(c[1]), "+f"(c[2]), "+f"(c[3])
        : "r"(a[0]), "r"(a[1]), "r"(a[2]), "r"(a[3]), "r"(b[0]), "r"(b[1]));
}

__global__ __launch_bounds__(128, 2) void k_gemm(const float* __restrict__ bias,
                                                 float* __restrict__ out) {
    extern __shared__ __align__(16) __half smem[];

    const int n0 = blockIdx.x * BN;   // 4 blocks (fast axis)
    const int m0 = blockIdx.y * BM;   // 400 blocks
    const int tid = threadIdx.x;      // 0..127
    const int wid = tid >> 5;         // 0..3
    const int lane = tid & 31;
    const int g  = lane >> 2;
    const int tg = lane & 3;
    const int mbase = (wid >> 1) * 64;   // 2 warp rows
    const int nbase = (wid & 1) * 64;    // 2 warp cols

    const uint32_t smem_base = (uint32_t)__cvta_generic_to_shared(smem);

    // cp.async: 4 A units + 4 B units of 16B per thread (512 units each tile)
    // unit = tid + i*128: row = unit>>2 (0..127), seg = (unit&3)*8 halves
    const int ld_row = tid >> 2;              // 0..31 (+i*32)
    const int ld_seg = (tid & 3) * 8;

    // ldmatrix bases (stage 0)
    uint32_t lmA[4];
    #pragma unroll
    for (int mi = 0; mi < 4; mi++)
        lmA[mi] = smem_base +
            (uint32_t)((mbase + mi*16 + (lane & 15))*KSTRIDE + ((lane >> 4) << 3))*2;
    uint32_t lmB[4];
    #pragma unroll
    for (int p = 0; p < 4; p++)
        lmB[p] = smem_base + ABUF_BYTES +
            (uint32_t)((nbase + p*16 + (((lane >> 4) & 1) << 3) + (lane & 7))*KSTRIDE
                       + (((lane >> 3) & 1) << 3))*2;

    float acc[4][8][4];
    #pragma unroll
    for (int mi = 0; mi < 4; mi++)
        #pragma unroll
        for (int ni = 0; ni < 8; ni++)
            #pragma unroll
            for (int r = 0; r < 4; r++) acc[mi][ni][r] = 0.f;

    const int NCHUNK = KDIM / BK;     // 16
    auto load_chunk = [&](int c) {
        if (c < NCHUNK) {
            uint32_t so = (uint32_t)(c % NSTAGE) * STAGE_BYTES;
            int kb = c * BK;
            #pragma unroll
            for (int i = 0; i < 4; i++) {
                int row = ld_row + i*32;
                uint32_t soff = so + (uint32_t)(row*KSTRIDE + ld_seg)*2;
                cp16(smem_base + soff,
                     g_vox + (size_t)(m0 + row)*KDIM + kb + ld_seg);
                cp16(smem_base + ABUF_BYTES + soff,
                     g_wlT + (size_t)(n0 + row)*KDIM + kb + ld_seg);
            }
        }
        cp_commit();
    };

    load_chunk(0);
    load_chunk(1);
    load_chunk(2);

    for (int c = 0; c < NCHUNK; c++) {
        cp_wait<2>();                 // chunk c resident
        __syncthreads();              // WAR guard on stage (c+3)%4

        load_chunk(c + 3);

        const uint32_t so = (uint32_t)(c % NSTAGE) * STAGE_BYTES;
        #pragma unroll
        for (int kc = 0; kc < BK; kc += 16) {
            uint32_t a[4][4], b[8][2];
            #pragma unroll
            for (int mi = 0; mi < 4; mi++)
                ldsm_x4(a[mi][0], a[mi][1], a[mi][2], a[mi][3],
                        lmA[mi] + so + kc*2);
            #pragma unroll
            for (int p = 0; p < 4; p++)
                ldsm_x4(b[2*p][0], b[2*p][1], b[2*p+1][0], b[2*p+1][1],
                        lmB[p] + so + kc*2);
            #pragma unroll
            for (int mi = 0; mi < 4; mi++)
                #pragma unroll
                for (int ni = 0; ni < 8; ni++)
                    mma_f16(acc[mi][ni], a[mi], b[ni]);
        }
    }

    // Epilogue: bias + relu + transposed store (coalesced along M)
    const int bidx  = m0 / PLANE;
    const int mrel0 = m0 - bidx*PLANE + mbase;
    #pragma unroll
    for (int ni = 0; ni < 8; ni++) {
        int n_e = n0 + nbase + ni*8 + 2*tg;
        float be = bias[n_e];
        float bo = bias[n_e + 1];
        float* ope = out + ((size_t)(bidx*CH + n_e))*PLANE;
        float* opo = ope + PLANE;
        #pragma unroll
        for (int mi = 0; mi < 4; mi++) {
            int moff = mrel0 + mi*16 + g;
            ope[moff    ] = fmaxf(acc[mi][ni][0] + be, 0.f);
            opo[moff    ] = fmaxf(acc[mi][ni][1] + bo, 0.f);
            ope[moff + 8] = fmaxf(acc[mi][ni][2] + be, 0.f);
            opo[moff + 8] = fmaxf(acc[mi][ni][3] + bo, 0.f);
        }
    }
}

// ---------------------------------------------------------------------------
extern "C" void kernel_launch(void* const* d_in, const int* in_sizes, int n_in,
                              void* d_out, int out_size) {
    const float* features = (const float*)d_in[0];   // [2,128,48,160]
    const float* calib    = (const float*)d_in[1];   // [2,3,4]
    const float* corners  = (const float*)d_in[2];   // [1,5,161,161,3]
    const float* W_lin    = (const float*)d_in[3];   // [512,512]
    const float* b_lin    = (const float*)d_in[4];   // [512]
    float* out = (float*)d_out;                      // [2,512,160,160]

    cudaFuncSetAttribute(k_gemm, cudaFuncAttributeMaxDynamicSharedMemorySize,
                         GEMM_SMEM);

    // 4 launches; k_gemm is the 4th (ncu capture window).
    k_prep<<<NPREP_TOTAL, 256>>>(features, W_lin, calib, corners);
    k_cumsum_h<<<BATCH*WF, CC>>>();
    k_sample<<<NCELL/8, 256>>>();
    k_gemm<<<dim3(CH/BN, MROWS/BM), 128, GEMM_SMEM>>>(b_lin, out);
}